// round 6
// baseline (speedup 1.0000x reference)
#include <cuda_runtime.h>

#define BSZ 2
#define SEQ 4096
#define DIM 1024
#define DIM4 (DIM / 4)         // 256 float4 per row
#define CHUNK 16
#define NCHUNK (SEQ / CHUNK)   // 256

// ---- scratch (__device__ globals) ----
__device__ int    g_pos[BSZ * SEQ];
__device__ float  g_pk [BSZ * SEQ];
__device__ int    g_idx[BSZ * SEQ];
__device__ float  g_Pc [BSZ * NCHUNK];
__device__ int    g_nb [BSZ];
__device__ float4 g_E4[BSZ * NCHUNK * DIM4];  // chunk-end local states (2 MB)
__device__ float4 g_S4[BSZ * NCHUNK * DIM4];  // incoming state per chunk (2 MB)
__device__ float4 g_Y4[BSZ * SEQ * DIM4];     // final token values (32 MB, nb rows used)

// ---------------------------------------------------------------------------
// Kernel 1: mask scan -> pos/pk/idx/nb + per-chunk decay products.
// One block per batch, 1024 threads (4 elems each).
// ---------------------------------------------------------------------------
__global__ void prep_kernel(const float* __restrict__ prob,
                            const void* __restrict__ mask_raw) {
    const int b = blockIdx.x;
    const int t = threadIdx.x;

    __shared__ int   s_w;
    __shared__ int   s_wsum[32];
    __shared__ int   s_total;
    __shared__ float s_pk[SEQ];   // compacted clipped p (16 KB)

    // ---- detect mask element width (1-byte bool vs 4-byte 0/1) ----
    if (t == 0) s_w = 0;
    __syncthreads();
    {
        const unsigned char* mb = (const unsigned char*)mask_raw;
        int f = 0;
        for (int j = t; j < (BSZ * SEQ) / 4; j += blockDim.x)
            f |= mb[4 * j + 1];
        if (f) s_w = 1;
    }
    __syncthreads();
    const int onebyte = s_w;

    const int base = t * 4;
    int m[4];
    if (onebyte) {
        const unsigned char* mb = (const unsigned char*)mask_raw + b * SEQ;
        #pragma unroll
        for (int j = 0; j < 4; j++) m[j] = mb[base + j] ? 1 : 0;
    } else {
        const int* mi = (const int*)mask_raw + b * SEQ;
        #pragma unroll
        for (int j = 0; j < 4; j++) m[j] = mi[base + j] ? 1 : 0;
    }
    int cnt = m[0] + m[1] + m[2] + m[3];

    // ---- block inclusive scan of per-thread counts ----
    int v = cnt;
    const int lane = t & 31, wid = t >> 5;
    #pragma unroll
    for (int o = 1; o < 32; o <<= 1) {
        int u = __shfl_up_sync(0xffffffffu, v, o);
        if (lane >= o) v += u;
    }
    if (lane == 31) s_wsum[wid] = v;
    __syncthreads();
    if (wid == 0) {
        int w = s_wsum[lane];
        #pragma unroll
        for (int o = 1; o < 32; o <<= 1) {
            int u = __shfl_up_sync(0xffffffffu, w, o);
            if (lane >= o) w += u;
        }
        s_wsum[lane] = w;
        if (lane == 31) s_total = w;
    }
    __syncthreads();

    int run = v - cnt + (wid ? s_wsum[wid - 1] : 0);  // exclusive prefix
    const int nb = s_total;
    if (t == 0) g_nb[b] = nb;

    const float* pb = prob + b * SEQ;
    #pragma unroll
    for (int j = 0; j < 4; j++) {
        const int l = base + j;
        if (m[j]) {
            float p = pb[l];
            p = fminf(fmaxf(p, 1e-4f), 0.9999f);
            g_pos[b * SEQ + run] = l;
            g_pk [b * SEQ + run] = p;
            s_pk[run] = p;
            run++;
        }
        g_idx[b * SEQ + l] = (run > 0) ? (run - 1) : 0;
    }
    __syncthreads();

    // ---- per-chunk decay products: 16-lane shuffle groups over smem ----
    const int nc = (nb + CHUNK - 1) / CHUNK;
    const int half = lane >> 4;           // which 16-lane group
    const int sub  = lane & 15;
    for (int c = wid * 2 + half; c < nc; c += 64) {
        const int k = c * CHUNK + sub;
        float a = (k < nb) ? (1.f - s_pk[k]) : 1.f;
        #pragma unroll
        for (int o = 8; o > 0; o >>= 1)
            a *= __shfl_xor_sync(0xffffffffu, a, o);
        if (sub == 0) g_Pc[b * NCHUNK + c] = a;
    }
}

// ---------------------------------------------------------------------------
// Kernel 2: chunk-local scans from zero -> chunk-end states g_E4.
// grid (NCHUNK, BSZ), 256 threads (one float4 column each).
// ---------------------------------------------------------------------------
__global__ void escan_kernel(const float* __restrict__ hidden) {
    const int b = blockIdx.y, c = blockIdx.x;
    const int d4 = threadIdx.x;
    const int nb = g_nb[b];
    const int k0 = c * CHUNK;
    if (k0 >= nb) return;
    const int n = min(CHUNK, nb - k0);

    __shared__ int   spos[CHUNK];
    __shared__ float spk [CHUNK];
    if (threadIdx.x < n) {
        spos[threadIdx.x] = g_pos[b * SEQ + k0 + threadIdx.x];
        spk [threadIdx.x] = g_pk [b * SEQ + k0 + threadIdx.x];
    }
    __syncthreads();

    const float4* hb = (const float4*)hidden + (size_t)b * SEQ * DIM4 + d4;
    float4 h[CHUNK];
    #pragma unroll
    for (int j = 0; j < CHUNK; j++)
        h[j] = (j < n) ? __ldg(hb + (size_t)spos[j] * DIM4)
                       : make_float4(0.f, 0.f, 0.f, 0.f);

    float4 s = make_float4(0.f, 0.f, 0.f, 0.f);
    #pragma unroll
    for (int j = 0; j < CHUNK; j++) {
        if (j < n) {
            const float p = spk[j], a = 1.f - p;
            s.x = fmaf(a, s.x, p * h[j].x);
            s.y = fmaf(a, s.y, p * h[j].y);
            s.z = fmaf(a, s.z, p * h[j].z);
            s.w = fmaf(a, s.w, p * h[j].w);
        }
    }
    g_E4[(size_t)(b * NCHUNK + c) * DIM4 + d4] = s;
}

// ---------------------------------------------------------------------------
// Kernel 3: serial combine across chunks -> g_S4 (incoming chunk states).
// grid (1, BSZ), 256 threads (one float4 column each), G-deep prefetch.
// ---------------------------------------------------------------------------
__global__ void combine_kernel() {
    const int b = blockIdx.y;
    const int d4 = threadIdx.x;
    const int nb = g_nb[b];
    const int nc = (nb + CHUNK - 1) / CHUNK;

    const float4* Eb = g_E4 + (size_t)(b * NCHUNK) * DIM4 + d4;
    const float*  Pb = g_Pc + b * NCHUNK;
    float4*       Sb = g_S4 + (size_t)(b * NCHUNK) * DIM4 + d4;

    float4 s = make_float4(0.f, 0.f, 0.f, 0.f);
    const int G = 16;
    float4 Ebuf[G];
    float  Pbuf[G];
    #pragma unroll
    for (int j = 0; j < G; j++) {
        Ebuf[j] = (j < nc) ? Eb[(size_t)j * DIM4] : make_float4(0.f, 0.f, 0.f, 0.f);
        Pbuf[j] = (j < nc) ? Pb[j] : 1.f;
    }
    for (int g = 0; g < NCHUNK && g < nc; g += G) {
        float4 En[G];
        float  Pn[G];
        #pragma unroll
        for (int j = 0; j < G; j++) {
            const int cc = g + G + j;
            En[j] = (cc < nc) ? Eb[(size_t)cc * DIM4] : make_float4(0.f, 0.f, 0.f, 0.f);
            Pn[j] = (cc < nc) ? Pb[cc] : 1.f;
        }
        #pragma unroll
        for (int j = 0; j < G; j++) {
            const int cc = g + j;
            if (cc < nc) {
                Sb[(size_t)cc * DIM4] = s;
                const float P = Pbuf[j];
                s.x = fmaf(P, s.x, Ebuf[j].x);
                s.y = fmaf(P, s.y, Ebuf[j].y);
                s.z = fmaf(P, s.z, Ebuf[j].z);
                s.w = fmaf(P, s.w, Ebuf[j].w);
            }
        }
        #pragma unroll
        for (int j = 0; j < G; j++) { Ebuf[j] = En[j]; Pbuf[j] = Pn[j]; }
    }
}

// ---------------------------------------------------------------------------
// Kernel 4: seeded re-scan -> final token values g_Y4 (compact, k-indexed).
// grid (NCHUNK, BSZ), 256 threads. h gather is L2-warm from escan.
// ---------------------------------------------------------------------------
__global__ void yfinal_kernel(const float* __restrict__ hidden) {
    const int b = blockIdx.y, c = blockIdx.x;
    const int d4 = threadIdx.x;
    const int nb = g_nb[b];
    const int k0 = c * CHUNK;
    if (k0 >= nb) return;
    const int n = min(CHUNK, nb - k0);

    __shared__ int   spos[CHUNK];
    __shared__ float spk [CHUNK];
    if (threadIdx.x < n) {
        spos[threadIdx.x] = g_pos[b * SEQ + k0 + threadIdx.x];
        spk [threadIdx.x] = g_pk [b * SEQ + k0 + threadIdx.x];
    }
    __syncthreads();

    const float4* hb = (const float4*)hidden + (size_t)b * SEQ * DIM4 + d4;
    float4 h[CHUNK];
    #pragma unroll
    for (int j = 0; j < CHUNK; j++)
        h[j] = (j < n) ? __ldg(hb + (size_t)spos[j] * DIM4)
                       : make_float4(0.f, 0.f, 0.f, 0.f);

    float4 s = g_S4[(size_t)(b * NCHUNK + c) * DIM4 + d4];
    float4* yb = g_Y4 + ((size_t)b * SEQ + k0) * DIM4 + d4;
    #pragma unroll
    for (int j = 0; j < CHUNK; j++) {
        if (j < n) {
            const float p = spk[j], a = 1.f - p;
            s.x = fmaf(a, s.x, p * h[j].x);
            s.y = fmaf(a, s.y, p * h[j].y);
            s.z = fmaf(a, s.z, p * h[j].z);
            s.w = fmaf(a, s.w, p * h[j].w);
            yb[(size_t)j * DIM4] = s;
        }
    }
}

// ---------------------------------------------------------------------------
// Kernel 5: expand: out[l,:] = Y[idx[l],:].  grid (SEQ, BSZ), 256 threads.
// Fully parallel coalesced stores; Y reads are L2 hits (runs share rows).
// ---------------------------------------------------------------------------
__global__ void expand_kernel(float* __restrict__ out) {
    const int l = blockIdx.x, b = blockIdx.y;
    const int t = threadIdx.x;
    const int k = g_idx[b * SEQ + l];
    const float4 v = g_Y4[((size_t)b * SEQ + k) * DIM4 + t];
    ((float4*)out)[((size_t)b * SEQ + l) * DIM4 + t] = v;
}

// ---------------------------------------------------------------------------
extern "C" void kernel_launch(void* const* d_in, const int* in_sizes, int n_in,
                              void* d_out, int out_size) {
    const float* hidden = (const float*)d_in[0];
    const float* prob   = (const float*)d_in[1];
    const void*  mask   = d_in[2];
    float* out = (float*)d_out;

    prep_kernel<<<BSZ, 1024>>>(prob, mask);
    escan_kernel<<<dim3(NCHUNK, BSZ), 256>>>(hidden);
    combine_kernel<<<dim3(1, BSZ), 256>>>();
    yfinal_kernel<<<dim3(NCHUNK, BSZ), 256>>>(hidden);
    expand_kernel<<<dim3(SEQ, BSZ), 256>>>(out);
}

// round 10
// speedup vs baseline: 1.0526x; 1.0526x over previous
#include <cuda_runtime.h>

#define BSZ 2
#define SEQ 4096
#define DIM 1024
#define DIM4 256               // float4 per row
#define NCB 128                // chunk-CTAs per batch
#define NBLK (NCB * BSZ)       // 256 total CTAs (co-resident: 2/SM * 148 = 296)
#define EPT (SEQ / 256)        // 16 sequence elems per thread in prep

// ---- global scratch ----
__device__ float4   g_E4[BSZ * NCB * DIM4];   // chunk-end local states
__device__ float4   g_S4[BSZ * NCB * DIM4];   // exclusive incoming state per chunk
__device__ unsigned g_cnt = 0;                // barrier arrival counter
__device__ unsigned g_gen = 0;                // barrier generation

// ---------------------------------------------------------------------------
__device__ __forceinline__ void grid_barrier(unsigned* mygen) {
    __syncthreads();
    if (threadIdx.x == 0) {
        __threadfence();
        unsigned a = atomicAdd(&g_cnt, 1u);
        if (a == NBLK - 1) {
            g_cnt = 0u;
            __threadfence();
            atomicExch(&g_gen, *mygen + 1u);
        } else {
            while ((int)(atomicAdd(&g_gen, 0u) - *mygen) <= 0) __nanosleep(128);
        }
        (*mygen)++;
    }
    __syncthreads();
}

// ---------------------------------------------------------------------------
// One fused kernel. grid (NCB, BSZ), 256 threads.
// ---------------------------------------------------------------------------
__global__ void __launch_bounds__(256, 2)
hnet_fused_kernel(const float* __restrict__ hidden,
                  const float* __restrict__ prob,
                  const void* __restrict__ mask_raw,
                  float* __restrict__ out) {
    const int b = blockIdx.y;
    const int c = blockIdx.x;
    const int t = threadIdx.x;
    const int lane = t & 31, wrp = t >> 5;

    __shared__ int   s_pos[SEQ];      // compacted boundary positions (16 KB)
    __shared__ float s_pk [SEQ];      // compacted clipped p (16 KB)
    __shared__ float s_P  [NCB];      // per-chunk decay products (combine only)
    __shared__ int   s_wsum[8];
    __shared__ int   s_nb;
    __shared__ int   s_w;

    unsigned mygen = 0;
    if (t == 0) mygen = atomicAdd(&g_gen, 0u);   // entry generation

    // ================= Phase 1: redundant per-CTA prep =====================
    // mask element-width detect: 4-byte 0/1 values have byte (4j+1)==0 always;
    // 1-byte bool at ~25% density has nonzero there w.p. ~1.
    if (t == 0) s_w = 0;
    __syncthreads();
    {
        const unsigned char* mb = (const unsigned char*)mask_raw;
        int f = 0;
        for (int j = t; j < (BSZ * SEQ) / 4; j += 256) f |= mb[4 * j + 1];
        if (f) s_w = 1;
    }
    __syncthreads();
    const int onebyte = s_w;

    // gather 16 mask bits per thread
    const int base = t * EPT;
    unsigned mbits = 0;
    if (onebyte) {
        const unsigned char* mb = (const unsigned char*)mask_raw + b * SEQ;
        #pragma unroll
        for (int j = 0; j < EPT; j++) if (mb[base + j]) mbits |= (1u << j);
    } else {
        const int* mi = (const int*)mask_raw + b * SEQ;
        #pragma unroll
        for (int j = 0; j < EPT; j++) if (mi[base + j]) mbits |= (1u << j);
    }
    int cnt = __popc(mbits);

    // block inclusive scan of per-thread counts (8 warps)
    int v = cnt;
    #pragma unroll
    for (int o = 1; o < 32; o <<= 1) {
        int u = __shfl_up_sync(0xffffffffu, v, o);
        if (lane >= o) v += u;
    }
    if (lane == 31) s_wsum[wrp] = v;
    __syncthreads();
    if (wrp == 0 && lane < 8) {
        int w = s_wsum[lane];
        #pragma unroll
        for (int o = 1; o < 8; o <<= 1) {
            int u = __shfl_up_sync(0xffu, w, o);
            if (lane >= o) w += u;
        }
        s_wsum[lane] = w;
        if (lane == 7) s_nb = w;
    }
    __syncthreads();

    int run = v - cnt + (wrp ? s_wsum[wrp - 1] : 0);   // exclusive prefix
    const int nb = s_nb;

    {
        const float* pb = prob + b * SEQ;
        #pragma unroll
        for (int j = 0; j < EPT; j++) {
            if (mbits & (1u << j)) {
                const int l = base + j;
                float p = pb[l];
                p = fminf(fmaxf(p, 1e-4f), 0.9999f);
                s_pos[run] = l;
                s_pk [run] = p;
                run++;
            }
        }
    }
    __syncthreads();

    // dynamic chunking: W tokens per CTA so all NCB CTAs are active
    const int W  = (nb + NCB - 1) / NCB;          // <= 32
    const int k0 = c * W;
    const int n  = max(0, min(W, nb - k0));

    const float4* hb = (const float4*)hidden + (size_t)b * SEQ * DIM4 + t;

    // ================= Phase 2: chunk-local scan -> E ======================
    if (n > 0) {
        float4 s = make_float4(0.f, 0.f, 0.f, 0.f);
        for (int j0 = 0; j0 < n; j0 += 8) {
            float4 h[8];
            #pragma unroll
            for (int i = 0; i < 8; i++) {
                const int j = j0 + i;
                h[i] = (j < n) ? __ldg(hb + (size_t)s_pos[k0 + j] * DIM4)
                               : make_float4(0.f, 0.f, 0.f, 0.f);
            }
            #pragma unroll
            for (int i = 0; i < 8; i++) {
                const int j = j0 + i;
                if (j < n) {
                    const float p = s_pk[k0 + j], a = 1.f - p;
                    s.x = fmaf(a, s.x, p * h[i].x);
                    s.y = fmaf(a, s.y, p * h[i].y);
                    s.z = fmaf(a, s.z, p * h[i].z);
                    s.w = fmaf(a, s.w, p * h[i].w);
                }
            }
        }
        g_E4[(size_t)(b * NCB + c) * DIM4 + t] = s;
    }

    grid_barrier(&mygen);   // ---- barrier 1: all E published ----

    // ================= Phase 3: serial combine -> S (c==0 CTAs) ===========
    if (c == 0) {
        const int nc = (nb + W - 1) / W;   // number of non-empty chunks
        // per-chunk scalar products from shared pk
        if (t < nc) {
            const int kk0 = t * W;
            const int nn = min(W, nb - kk0);
            float q = 1.f;
            for (int j = 0; j < nn; j++) q *= (1.f - s_pk[kk0 + j]);
            s_P[t] = q;
        }
        __syncthreads();

        const float4* Eb = g_E4 + (size_t)(b * NCB) * DIM4 + t;
        float4*       Sb = g_S4 + (size_t)(b * NCB) * DIM4 + t;

        float4 S = make_float4(0.f, 0.f, 0.f, 0.f);
        const int G = 8;
        float4 Ebuf[G];
        float  Pbuf[G];
        #pragma unroll
        for (int i = 0; i < G; i++) {
            Ebuf[i] = (i < nc) ? __ldcg(Eb + (size_t)i * DIM4)
                               : make_float4(0.f, 0.f, 0.f, 0.f);
            Pbuf[i] = (i < nc) ? s_P[i] : 1.f;
        }
        for (int g = 0; g < nc; g += G) {
            float4 En[G];
            float  Pn[G];
            #pragma unroll
            for (int i = 0; i < G; i++) {
                const int cc = g + G + i;
                En[i] = (cc < nc) ? __ldcg(Eb + (size_t)cc * DIM4)
                                  : make_float4(0.f, 0.f, 0.f, 0.f);
                Pn[i] = (cc < nc) ? s_P[cc] : 1.f;
            }
            #pragma unroll
            for (int i = 0; i < G; i++) {
                const int cc = g + i;
                if (cc < nc) {
                    Sb[(size_t)cc * DIM4] = S;   // exclusive prefix
                    const float P = Pbuf[i];
                    S.x = fmaf(P, S.x, Ebuf[i].x);
                    S.y = fmaf(P, S.y, Ebuf[i].y);
                    S.z = fmaf(P, S.z, Ebuf[i].z);
                    S.w = fmaf(P, S.w, Ebuf[i].w);
                }
            }
            #pragma unroll
            for (int i = 0; i < G; i++) { Ebuf[i] = En[i]; Pbuf[i] = Pn[i]; }
        }
        __threadfence();
    }

    grid_barrier(&mygen);   // ---- barrier 2: all S published ----

    // ======== Phase 4: seeded rescan + run-expansion to out ===============
    if (n > 0) {
        float4 s = __ldcg(&g_S4[(size_t)(b * NCB + c) * DIM4 + t]);
        float4* ob = (float4*)out + (size_t)b * SEQ * DIM4 + t;

        for (int j0 = 0; j0 < n; j0 += 8) {
            float4 h[8];
            #pragma unroll
            for (int i = 0; i < 8; i++) {
                const int j = j0 + i;
                h[i] = (j < n) ? __ldg(hb + (size_t)s_pos[k0 + j] * DIM4)
                               : make_float4(0.f, 0.f, 0.f, 0.f);
            }
            #pragma unroll
            for (int i = 0; i < 8; i++) {
                const int j = j0 + i;
                if (j < n) {
                    const int k = k0 + j;
                    const float p = s_pk[k], a = 1.f - p;
                    s.x = fmaf(a, s.x, p * h[i].x);
                    s.y = fmaf(a, s.y, p * h[i].y);
                    s.z = fmaf(a, s.z, p * h[i].z);
                    s.w = fmaf(a, s.w, p * h[i].w);
                    const int start = (k == 0) ? 0 : s_pos[k];
                    const int end   = (k + 1 < nb) ? s_pos[k + 1] : SEQ;
                    for (int l = start; l < end; l++)
                        ob[(size_t)l * DIM4] = s;
                }
            }
        }
    }
}

// ---------------------------------------------------------------------------
extern "C" void kernel_launch(void* const* d_in, const int* in_sizes, int n_in,
                              void* d_out, int out_size) {
    const float* hidden = (const float*)d_in[0];
    const float* prob   = (const float*)d_in[1];
    const void*  mask   = d_in[2];
    float* out = (float*)d_out;

    hnet_fused_kernel<<<dim3(NCB, BSZ), 256>>>(hidden, prob, mask, out);
}